// round 1
// baseline (speedup 1.0000x reference)
#include <cuda_runtime.h>
#include <cstdint>

// Correlation: out[b,d,h,w] = (1/256) * sum_c in1[b,c,h,w] * in2[b,c,h+dy,w+dx]
//   B=16, C=256, H=48, W=64; dy,dx in {-20,-18,...,20} (21 each, d = jy*21+jx),
//   zero outside bounds. Output (16, 441, 48, 64) fp32.
//
// One CTA per (b,h). 352 threads: tid -> (u4 = tid%16 in [0,16), jy = tid/16 in [0,21)).
// Thread owns w in [4*u4, 4*u4+4) x all 21 jx for its jy -> 84 fp32 accumulators.
// Channels streamed in CC=2 chunks through double-buffered shared memory via
// cp.async (zero-fill OOB chunks with src-size 0). Inner loop: rolling float4
// window over the 44-float in2 span -> 13 LDS.128 feed 84 FFMA per channel.

#define NB 16
#define NC 256
#define NH 48
#define NW 64
#define ND 21
#define NDISP (ND * ND)
#define WINP 104          // in2 window per row: cols [-20, 84) -> 104 floats
#define CC 2              // channels per chunk
#define NK (NC / CC)      // 128 chunks
#define NTHREADS 352
#define NACTIVE (16 * ND) // 336

// per-chunk fill work items: per cc: 16 in1 chunks + 21*26 in2 chunks = 562
#define ITEMS_PER_CC 562
#define ITEMS_TOTAL (CC * ITEMS_PER_CC)

__device__ __forceinline__ unsigned smem_u32(const void* p) {
    return (unsigned)__cvta_generic_to_shared(p);
}
__device__ __forceinline__ void cp16(unsigned sdst, const void* gsrc, int nbytes) {
    asm volatile("cp.async.cg.shared.global [%0], [%1], 16, %2;\n"
                 :: "r"(sdst), "l"(gsrc), "r"(nbytes));
}

__global__ __launch_bounds__(NTHREADS, 1)
void corr_kernel(const float* __restrict__ in1,
                 const float* __restrict__ in2,
                 float* __restrict__ out) {
    __shared__ float s1[2][CC][NW];            // in1 row slice
    __shared__ float s2[2][CC][ND][WINP];      // 21 shifted in2 rows

    const int h   = blockIdx.x;   // [0,48)
    const int b   = blockIdx.y;   // [0,16)
    const int tid = threadIdx.x;
    const int u4  = tid & 15;     // w-quad index
    const int jy  = tid >> 4;     // dy index (valid < 21)
    const bool active = (tid < NACTIVE);

    const float* in1bh = in1 + ((size_t)b * NC) * (NH * NW) + (size_t)h * NW;
    const float* in2b  = in2 + ((size_t)b * NC) * (NH * NW);

    float acc[ND][4];
#pragma unroll
    for (int j = 0; j < ND; ++j) {
        acc[j][0] = 0.f; acc[j][1] = 0.f; acc[j][2] = 0.f; acc[j][3] = 0.f;
    }

    // ---- chunk fill: stage channels [k*CC, k*CC+CC) into buffer `buf` ----
    auto fill = [&](int k, int buf) {
        const int cbase = k * CC;
        for (int i = tid; i < ITEMS_TOTAL; i += NTHREADS) {
            const int cc = i / ITEMS_PER_CC;
            const int r  = i - cc * ITEMS_PER_CC;
            const int c  = cbase + cc;
            if (r < 16) {
                // in1[b, c, h, 4r .. 4r+3]
                unsigned dst = smem_u32(&s1[buf][cc][r * 4]);
                const float* src = in1bh + (size_t)c * (NH * NW) + r * 4;
                cp16(dst, src, 16);
            } else {
                const int rr  = r - 16;
                const int row = rr / 26;       // dy index [0,21)
                const int q   = rr - row * 26; // 16B chunk within 104-float window
                const int gr  = h + 2 * row - 20;
                const bool ok = (gr >= 0) && (gr < NH) && (q >= 5) && (q < 21);
                unsigned dst = smem_u32(&s2[buf][cc][row][q * 4]);
                const float* src = ok
                    ? (in2b + ((size_t)c * NH + gr) * NW + (q * 4 - 20))
                    : in2b; // safe dummy; src-size 0 => pure zero-fill
                cp16(dst, src, ok ? 16 : 0);
            }
        }
    };

    fill(0, 0);
    asm volatile("cp.async.commit_group;\n");

    for (int k = 0; k < NK; ++k) {
        const int kn = (k + 1 < NK) ? (k + 1) : k;  // clamped harmless refill
        fill(kn, (k + 1) & 1);
        asm volatile("cp.async.commit_group;\n");
        asm volatile("cp.async.wait_group 1;\n");   // chunk k resident
        __syncthreads();

        if (active) {
            const int buf = k & 1;
#pragma unroll
            for (int cc = 0; cc < CC; ++cc) {
                const float4 a = *(const float4*)&s1[buf][cc][4 * u4];
                const float* win = &s2[buf][cc][jy][4 * u4];
                float4 b0 = *(const float4*)&win[0];
#pragma unroll
                for (int t = 0; t < 11; ++t) {
                    float4 b1 = b0;
                    if (t < 10) b1 = *(const float4*)&win[4 * t + 4];
                    const int j0 = 2 * t;
                    // jx = 2t : in2 offsets 4u4+4t+{0..3} = b0
                    acc[j0][0] += a.x * b0.x;
                    acc[j0][1] += a.y * b0.y;
                    acc[j0][2] += a.z * b0.z;
                    acc[j0][3] += a.w * b0.w;
                    if (t < 10) {
                        // jx = 2t+1 : in2 offsets 4u4+4t+2+{0..3} = b0.zw, b1.xy
                        acc[j0 + 1][0] += a.x * b0.z;
                        acc[j0 + 1][1] += a.y * b0.w;
                        acc[j0 + 1][2] += a.z * b1.x;
                        acc[j0 + 1][3] += a.w * b1.y;
                        b0 = b1;
                    }
                }
            }
        }
        __syncthreads();
    }

    if (active) {
        const float inv = 1.0f / 256.0f;
        // out[b, d = jy*21 + j, h, 4*u4 .. +3]
        float* obase = out + (((size_t)b * NDISP + (size_t)jy * ND) * NH + h) * NW + 4 * u4;
#pragma unroll
        for (int j = 0; j < ND; ++j) {
            float4 v;
            v.x = acc[j][0] * inv;
            v.y = acc[j][1] * inv;
            v.z = acc[j][2] * inv;
            v.w = acc[j][3] * inv;
            *(float4*)(obase + (size_t)j * (NH * NW)) = v;
        }
    }
}

extern "C" void kernel_launch(void* const* d_in, const int* in_sizes, int n_in,
                              void* d_out, int out_size) {
    const float* in1 = (const float*)d_in[0];
    const float* in2 = (const float*)d_in[1];
    float* out = (float*)d_out;
    dim3 grid(NH, NB);
    corr_kernel<<<grid, NTHREADS>>>(in1, in2, out);
}

// round 6
// speedup vs baseline: 1.8426x; 1.8426x over previous
#include <cuda_runtime.h>
#include <cstdint>

// Correlation: out[b,d,h,w] = (1/256) * sum_c in1[b,c,h,w] * in2[b,c,h+dy,w+dx]
//   B=16, C=256, H=48, W=64; dy,dx in {-20,...,20} step 2 (21 each), zero padded.
//
// One CTA per (b,h), 352 threads. Active 336 threads: tid -> r=tid&15, jy=tid>>4;
// uoct=r>>1 (w base W0=8*uoct), half=r&1 (jx block). Thread computes 8 w x 11 jx
// (half=1 uses 10, acc[0] is scratch). Channels stream in CC=2 chunks through a
// double-buffered smem stage via cp.async; per-thread fill descriptors are
// precomputed ONCE (<=2 per thread), OOB pad regions are zeroed ONCE.

#define NB 16
#define NC 256
#define NH 48
#define NW 64
#define ND 21
#define NDISP 441
#define WINP 104
#define CC 2
#define NK (NC / CC)
#define NTHREADS 352
#define NACTIVE 336
#define HW (NH * NW)

#define CCF 2248                 // floats per cc block: 64 + 21*104 = 2248
#define BUFF (CC * CCF)          // floats per buffer
#define BUFBYTES (BUFF * 4)
#define SRCSTRIDE (CC * HW * 4)  // global src advance per chunk (bytes)

static_assert(CCF == 64 + ND * WINP, "cc block size mismatch");
static_assert((CCF * 4) % 16 == 0, "cc block must stay 16B aligned");

__device__ __forceinline__ unsigned smem_u32(const void* p) {
    return (unsigned)__cvta_generic_to_shared(p);
}
__device__ __forceinline__ void cp16(unsigned sdst, const void* gsrc) {
    asm volatile("cp.async.cg.shared.global [%0], [%1], 16;\n" :: "r"(sdst), "l"(gsrc));
}

__global__ __launch_bounds__(NTHREADS, 1)
void corr_kernel(const float* __restrict__ in1,
                 const float* __restrict__ in2,
                 float* __restrict__ out) {
    __shared__ float sm[2][BUFF];

    const int h   = blockIdx.x;
    const int b   = blockIdx.y;
    const int tid = threadIdx.x;
    const int r    = tid & 15;
    const int jy   = tid >> 4;          // valid < 21
    const int uoct = r >> 1;
    const int half = r & 1;
    const int W0   = uoct * 8;
    const int wb   = W0 + (half ? 20 : 0);  // window float base (16B aligned)
    const bool active = (tid < NACTIVE);

    // ---- zero both buffers once (pad regions stay zero forever) ----
    {
        float4 z = make_float4(0.f, 0.f, 0.f, 0.f);
        float4* p = (float4*)&sm[0][0];
        #pragma unroll
        for (int i = 0; i < (2 * BUFF / 4 + NTHREADS - 1) / NTHREADS; ++i) {
            int idx = tid + i * NTHREADS;
            if (idx < 2 * BUFF / 4) p[idx] = z;
        }
    }

    // ---- precompute fill descriptors (valid 16B chunks only) ----
    const int row_lo = max(0, (21 - h) >> 1);
    const int row_hi = min(20, (67 - h) >> 1);
    const int nv     = row_hi - row_lo + 1;
    const int per    = 16 * (1 + nv);       // items per cc
    const int total  = CC * per;            // <= 704 = 2*NTHREADS

    unsigned dstoff[2];
    const char* srcp[2];
    bool val[2];
    #pragma unroll
    for (int s = 0; s < 2; ++s) {
        const int i = tid + s * NTHREADS;
        val[s] = (i < total);
        dstoff[s] = 0; srcp[s] = (const char*)in1;
        if (val[s]) {
            const int cc = i / per;
            const int rem = i - cc * per;
            if (rem < 16) {
                dstoff[s] = (cc * CCF + rem * 4) * 4;
                srcp[s] = (const char*)(in1 + (((size_t)b * NC + cc) * NH + h) * NW + rem * 4);
            } else {
                const int rr  = rem - 16;
                const int v   = rr >> 4;
                const int q   = (rr & 15) + 5;
                const int row = row_lo + v;
                const int gr  = h + 2 * row - 20;
                dstoff[s] = (cc * CCF + 64 + row * WINP + q * 4) * 4;
                srcp[s] = (const char*)(in2 + (((size_t)b * NC + cc) * NH + gr) * NW + (q * 4 - 20));
            }
        }
    }

    const unsigned sbase = smem_u32(&sm[0][0]);

    __syncthreads();   // zeros visible before any cp.async lands

    // prologue: fill chunk 0 into buffer 0
    #pragma unroll
    for (int s = 0; s < 2; ++s) {
        if (val[s]) { cp16(sbase + dstoff[s], srcp[s]); srcp[s] += SRCSTRIDE; }
    }
    asm volatile("cp.async.commit_group;\n");

    float acc[11][8];
    #pragma unroll
    for (int j = 0; j < 11; ++j)
        #pragma unroll
        for (int i = 0; i < 8; ++i) acc[j][i] = 0.f;

    for (int k = 0; k < NK; ++k) {
        if (k + 1 < NK) {
            const unsigned boff = ((k + 1) & 1) * BUFBYTES;
            #pragma unroll
            for (int s = 0; s < 2; ++s) {
                if (val[s]) { cp16(sbase + boff + dstoff[s], srcp[s]); srcp[s] += SRCSTRIDE; }
            }
        }
        asm volatile("cp.async.commit_group;\n");
        asm volatile("cp.async.wait_group 1;\n");
        __syncthreads();

        if (active) {
            const float* B = &sm[k & 1][0];
            #pragma unroll
            for (int cc = 0; cc < CC; ++cc) {
                const float* s1r = B + cc * CCF;
                const float* s2r = B + cc * CCF + 64 + jy * WINP;
                float a[8];
                *(float4*)&a[0] = *(const float4*)&s1r[W0];
                *(float4*)&a[4] = *(const float4*)&s1r[W0 + 4];
                float f[28];
                #pragma unroll
                for (int t = 0; t < 7; ++t)
                    *(float4*)&f[4 * t] = *(const float4*)&s2r[wb + 4 * t];
                // acc[j] holds jx = half*10 + j ; for half=1, acc[0] is scratch.
                #pragma unroll
                for (int j = 0; j < 11; ++j)
                    #pragma unroll
                    for (int i = 0; i < 8; ++i)
                        acc[j][i] += a[i] * f[2 * j + i];
            }
        }
        __syncthreads();
    }

    if (active) {
        const float inv = 1.0f / 256.0f;
        #pragma unroll
        for (int j = 0; j < 11; ++j) {
            if (j >= half) {
                const int jx = half * 10 + j;
                float* o = out + ((((size_t)b * NDISP + (size_t)jy * ND + jx) * NH + h) * NW) + W0;
                float4 v0, v1;
                v0.x = acc[j][0] * inv; v0.y = acc[j][1] * inv;
                v0.z = acc[j][2] * inv; v0.w = acc[j][3] * inv;
                v1.x = acc[j][4] * inv; v1.y = acc[j][5] * inv;
                v1.z = acc[j][6] * inv; v1.w = acc[j][7] * inv;
                *(float4*)o = v0;
                *(float4*)(o + 4) = v1;
            }
        }
    }
}

extern "C" void kernel_launch(void* const* d_in, const int* in_sizes, int n_in,
                              void* d_out, int out_size) {
    const float* in1 = (const float*)d_in[0];
    const float* in2 = (const float*)d_in[1];
    float* out = (float*)d_out;
    dim3 grid(NH, NB);
    corr_kernel<<<grid, NTHREADS>>>(in1, in2, out);
}

// round 7
// speedup vs baseline: 2.0938x; 1.1363x over previous
#include <cuda_runtime.h>
#include <cstdint>
#include <cstring>

// Correlation: out[b,d,h,w] = (1/256) * sum_c in1[b,c,h,w] * in2[b,c,h+dy,w+dx]
//   B=16, C=256, H=48, W=64; dy,dx in {-20,...,20} step 2 (21 each), zero padded.
//
// Grid (48, 16, 2): CTA per (h, b, jy-group). Group 0: jy 0..10, group 1: jy 11..20.
// 176 threads: tid -> r=tid&15 (uoct=r>>1 -> W0=8*uoct, half=r&1), jyl=tid>>4.
// Thread computes 8 w x 11 jx via packed fma.rn.f32x2 (44 b64 accumulators).
// Channels stream in CC=2 chunks through double-buffered smem via cp.async;
// fill descriptors precomputed once (<=3/thread), pad regions zeroed once.

#define NB 16
#define NC 256
#define NH 48
#define NW 64
#define ND 21
#define NDISP 441
#define WINP 104
#define CC 2
#define NK (NC / CC)
#define NTHREADS 176
#define NROWS 11
#define HW (NH * NW)
#define SD 3                      // descriptor slots per thread

#define CCF (64 + NROWS * WINP)   // 1208 floats per cc block
#define BUFF (CC * CCF)           // 2416 floats per buffer
#define BUFBYTES (BUFF * 4)
#define SRCSTRIDE (CC * HW * 4)   // global src advance per chunk (bytes)

static_assert((CCF * 4) % 16 == 0, "cc block must stay 16B aligned");
static_assert(SD * NTHREADS >= CC * 16 * (1 + NROWS + 1), "descriptor slots");

__device__ __forceinline__ unsigned smem_u32(const void* p) {
    return (unsigned)__cvta_generic_to_shared(p);
}
__device__ __forceinline__ void cp16(unsigned sdst, const void* gsrc) {
    asm volatile("cp.async.cg.shared.global [%0], [%1], 16;\n" :: "r"(sdst), "l"(gsrc));
}
__device__ __forceinline__ void fma2(unsigned long long& d,
                                     unsigned long long a,
                                     unsigned long long b) {
    asm("fma.rn.f32x2 %0, %1, %2, %3;" : "=l"(d) : "l"(a), "l"(b), "l"(d));
}

__global__ __launch_bounds__(NTHREADS, 2)
void corr_kernel(const float* __restrict__ in1,
                 const float* __restrict__ in2,
                 float* __restrict__ out) {
    __shared__ float sm[2][BUFF];

    const int h    = blockIdx.x;
    const int b    = blockIdx.y;
    const int g    = blockIdx.z;        // jy group
    const int jylo = g ? 11 : 0;
    const int njy  = g ? 10 : 11;
    const int tid  = threadIdx.x;
    const int r    = tid & 15;
    const int jyl  = tid >> 4;          // local jy index, valid < njy
    const int uoct = r >> 1;
    const int half = r & 1;
    const int W0   = uoct * 8;
    const int wb   = W0 + (half ? 20 : 0);  // window float base (16B aligned)
    const bool active = (jyl < njy);

    // ---- zero both buffers once (pad regions stay zero forever) ----
    {
        float4 z = make_float4(0.f, 0.f, 0.f, 0.f);
        float4* p = (float4*)&sm[0][0];
        #pragma unroll
        for (int i = 0; i < (2 * BUFF / 4 + NTHREADS - 1) / NTHREADS; ++i) {
            int idx = tid + i * NTHREADS;
            if (idx < 2 * BUFF / 4) p[idx] = z;
        }
    }

    // ---- precompute fill descriptors (valid 16B chunks only) ----
    const int row_lo_g = max(0, (21 - h) >> 1);      // global valid dy rows
    const int row_hi_g = min(20, (67 - h) >> 1);
    const int rlo = max(row_lo_g, jylo);
    const int rhi = min(row_hi_g, jylo + njy - 1);
    const int nv  = (rhi >= rlo) ? (rhi - rlo + 1) : 0;
    const int per   = 16 * (1 + nv);    // items per cc
    const int total = CC * per;         // <= 2*16*12 = 384 <= SD*NTHREADS

    unsigned dstoff[SD];
    const char* srcp[SD];
    bool val[SD];
    #pragma unroll
    for (int s = 0; s < SD; ++s) {
        const int i = tid + s * NTHREADS;
        val[s] = (i < total);
        dstoff[s] = 0; srcp[s] = (const char*)in1;
        if (val[s]) {
            const int cc  = i / per;
            const int rem = i - cc * per;
            if (rem < 16) {
                dstoff[s] = (cc * CCF + rem * 4) * 4;
                srcp[s] = (const char*)(in1 + (((size_t)b * NC + cc) * NH + h) * NW + rem * 4);
            } else {
                const int rr  = rem - 16;
                const int v   = rr >> 4;
                const int q   = (rr & 15) + 5;       // 16B chunk in [5,21) of window
                const int row = rlo + v;             // global dy row
                const int gr  = h + 2 * row - 20;    // in-bounds by construction
                dstoff[s] = (cc * CCF + 64 + (row - jylo) * WINP + q * 4) * 4;
                srcp[s] = (const char*)(in2 + (((size_t)b * NC + cc) * NH + gr) * NW + (q * 4 - 20));
            }
        }
    }

    const unsigned sbase = smem_u32(&sm[0][0]);

    __syncthreads();   // zeros visible before any cp.async lands

    // prologue: fill chunk 0 into buffer 0
    #pragma unroll
    for (int s = 0; s < SD; ++s) {
        if (val[s]) { cp16(sbase + dstoff[s], srcp[s]); srcp[s] += SRCSTRIDE; }
    }
    asm volatile("cp.async.commit_group;\n");

    unsigned long long acc2[11][4];
    #pragma unroll
    for (int j = 0; j < 11; ++j)
        #pragma unroll
        for (int p = 0; p < 4; ++p) acc2[j][p] = 0ull;

    for (int k = 0; k < NK; ++k) {
        if (k + 1 < NK) {
            const unsigned boff = ((k + 1) & 1) * BUFBYTES;
            #pragma unroll
            for (int s = 0; s < SD; ++s) {
                if (val[s]) { cp16(sbase + boff + dstoff[s], srcp[s]); srcp[s] += SRCSTRIDE; }
            }
        }
        asm volatile("cp.async.commit_group;\n");
        asm volatile("cp.async.wait_group 1;\n");
        __syncthreads();

        if (active) {
            const float* B = &sm[k & 1][0];
            #pragma unroll
            for (int cc = 0; cc < CC; ++cc) {
                const float* s1r = B + cc * CCF;
                const float* s2r = B + cc * CCF + 64 + jyl * WINP;
                unsigned long long a2[4];
                {
                    ulonglong2 t0 = *(const ulonglong2*)&s1r[W0];
                    ulonglong2 t1 = *(const ulonglong2*)&s1r[W0 + 4];
                    a2[0] = t0.x; a2[1] = t0.y; a2[2] = t1.x; a2[3] = t1.y;
                }
                unsigned long long f2[14];
                #pragma unroll
                for (int t = 0; t < 7; ++t) {
                    ulonglong2 v = *(const ulonglong2*)&s2r[wb + 4 * t];
                    f2[2 * t] = v.x; f2[2 * t + 1] = v.y;
                }
                // acc2[j][p] covers out w = W0+2p..2p+1, jx = half*10 + j.
                #pragma unroll
                for (int j = 0; j < 11; ++j)
                    #pragma unroll
                    for (int p = 0; p < 4; ++p)
                        fma2(acc2[j][p], a2[p], f2[j + p]);
            }
        }
        __syncthreads();
    }

    if (active) {
        const float inv = 1.0f / 256.0f;
        const int jy = jylo + jyl;
        #pragma unroll
        for (int j = 0; j < 11; ++j) {
            if (j >= half) {                  // half=1: j=0 duplicates jx=10
                const int jx = half * 10 + j;
                float* o = out + ((((size_t)b * NDISP + (size_t)jy * ND + jx) * NH + h) * NW) + W0;
                float2 u[4];
                #pragma unroll
                for (int p = 0; p < 4; ++p)
                    memcpy(&u[p], &acc2[j][p], 8);
                float4 v0, v1;
                v0.x = u[0].x * inv; v0.y = u[0].y * inv;
                v0.z = u[1].x * inv; v0.w = u[1].y * inv;
                v1.x = u[2].x * inv; v1.y = u[2].y * inv;
                v1.z = u[3].x * inv; v1.w = u[3].y * inv;
                *(float4*)o = v0;
                *(float4*)(o + 4) = v1;
            }
        }
    }
}

extern "C" void kernel_launch(void* const* d_in, const int* in_sizes, int n_in,
                              void* d_out, int out_size) {
    const float* in1 = (const float*)d_in[0];
    const float* in2 = (const float*)d_in[1];
    float* out = (float*)d_out;
    dim3 grid(NH, NB, 2);
    corr_kernel<<<grid, NTHREADS>>>(in1, in2, out);
}

// round 12
// speedup vs baseline: 2.3861x; 1.1396x over previous
#include <cuda_runtime.h>
#include <cstdint>
#include <cstring>

// Correlation: out[b,d,h,w] = (1/256) * sum_c in1[b,c,h,w] * in2[b,c,h+dy,w+dx]
//   B=16, C=256, H=48, W=64; dy,dx in {-20,...,20} step 2 (21 each), zero padded.
//
// Grid (48, 16, 2): CTA per (h, b, jy-group). Group 0: jy 0..10, group 1: jy 11..20.
// 176 threads: tid -> r=tid&15 (uoct=r>>1 -> W0=8*uoct, half=r&1), jyl=tid>>4.
// Thread computes 8 w x 11 jx via packed fma.rn.f32x2 (44 b64 accumulators).
// Channels stream in CC=4 chunks through double-buffered smem via cp.async;
// fill descriptors precomputed once (<=5/thread), pad regions zeroed once.

#define NB 16
#define NC 256
#define NH 48
#define NW 64
#define ND 21
#define NDISP 441
#define WINP 104
#define CC 4
#define NK (NC / CC)
#define NTHREADS 176
#define NROWS 11
#define HW (NH * NW)
#define SD 5                      // descriptor slots per thread

#define CCF (64 + NROWS * WINP)   // 1208 floats per cc block
#define BUFF (CC * CCF)           // 4832 floats per buffer
#define BUFBYTES (BUFF * 4)
#define SRCSTRIDE (CC * HW * 4)   // global src advance per chunk (bytes)

static_assert((CCF * 4) % 16 == 0, "cc block must stay 16B aligned");
static_assert(SD * NTHREADS >= CC * 16 * (1 + NROWS + 1), "descriptor slots");
static_assert(2 * BUFBYTES <= 48 * 1024, "static smem limit");

__device__ __forceinline__ unsigned smem_u32(const void* p) {
    return (unsigned)__cvta_generic_to_shared(p);
}
__device__ __forceinline__ void cp16(unsigned sdst, const void* gsrc) {
    asm volatile("cp.async.cg.shared.global [%0], [%1], 16;\n" :: "r"(sdst), "l"(gsrc));
}
__device__ __forceinline__ void fma2(unsigned long long& d,
                                     unsigned long long a,
                                     unsigned long long b) {
    asm("fma.rn.f32x2 %0, %1, %2, %3;" : "=l"(d) : "l"(a), "l"(b), "l"(d));
}

__global__ __launch_bounds__(NTHREADS, 2)
void corr_kernel(const float* __restrict__ in1,
                 const float* __restrict__ in2,
                 float* __restrict__ out) {
    __shared__ float sm[2][BUFF];

    const int h    = blockIdx.x;
    const int b    = blockIdx.y;
    const int g    = blockIdx.z;        // jy group
    const int jylo = g ? 11 : 0;
    const int njy  = g ? 10 : 11;
    const int tid  = threadIdx.x;
    const int r    = tid & 15;
    const int jyl  = tid >> 4;          // local jy index, valid < njy
    const int uoct = r >> 1;
    const int half = r & 1;
    const int W0   = uoct * 8;
    const int wb   = W0 + (half ? 20 : 0);  // window float base (16B aligned)
    const bool active = (jyl < njy);

    // ---- zero both buffers once (pad regions stay zero forever) ----
    {
        float4 z = make_float4(0.f, 0.f, 0.f, 0.f);
        float4* p = (float4*)&sm[0][0];
        #pragma unroll
        for (int i = 0; i < (2 * BUFF / 4 + NTHREADS - 1) / NTHREADS; ++i) {
            int idx = tid + i * NTHREADS;
            if (idx < 2 * BUFF / 4) p[idx] = z;
        }
    }

    // ---- precompute fill descriptors (valid 16B chunks only) ----
    const int row_lo_g = max(0, (21 - h) >> 1);      // global valid dy rows
    const int row_hi_g = min(20, (67 - h) >> 1);
    const int rlo = max(row_lo_g, jylo);
    const int rhi = min(row_hi_g, jylo + njy - 1);
    const int nv  = (rhi >= rlo) ? (rhi - rlo + 1) : 0;
    const int per   = 16 * (1 + nv);    // items per cc
    const int total = CC * per;         // <= 4*16*12 = 768 <= SD*NTHREADS

    unsigned dstoff[SD];
    const char* srcp[SD];
    bool val[SD];
    #pragma unroll
    for (int s = 0; s < SD; ++s) {
        const int i = tid + s * NTHREADS;
        val[s] = (i < total);
        dstoff[s] = 0; srcp[s] = (const char*)in1;
        if (val[s]) {
            const int cc  = i / per;
            const int rem = i - cc * per;
            if (rem < 16) {
                dstoff[s] = (cc * CCF + rem * 4) * 4;
                srcp[s] = (const char*)(in1 + (((size_t)b * NC + cc) * NH + h) * NW + rem * 4);
            } else {
                const int rr  = rem - 16;
                const int v   = rr >> 4;
                const int q   = (rr & 15) + 5;       // 16B chunk in [5,21) of window
                const int row = rlo + v;             // global dy row
                const int gr  = h + 2 * row - 20;    // in-bounds by construction
                dstoff[s] = (cc * CCF + 64 + (row - jylo) * WINP + q * 4) * 4;
                srcp[s] = (const char*)(in2 + (((size_t)b * NC + cc) * NH + gr) * NW + (q * 4 - 20));
            }
        }
    }

    const unsigned sbase = smem_u32(&sm[0][0]);

    __syncthreads();   // zeros visible before any cp.async lands

    // prologue: fill chunk 0 into buffer 0
    #pragma unroll
    for (int s = 0; s < SD; ++s) {
        if (val[s]) { cp16(sbase + dstoff[s], srcp[s]); srcp[s] += SRCSTRIDE; }
    }
    asm volatile("cp.async.commit_group;\n");

    unsigned long long acc2[11][4];
    #pragma unroll
    for (int j = 0; j < 11; ++j)
        #pragma unroll
        for (int p = 0; p < 4; ++p) acc2[j][p] = 0ull;

    for (int k = 0; k < NK; ++k) {
        if (k + 1 < NK) {
            const unsigned boff = ((k + 1) & 1) * BUFBYTES;
            #pragma unroll
            for (int s = 0; s < SD; ++s) {
                if (val[s]) { cp16(sbase + boff + dstoff[s], srcp[s]); srcp[s] += SRCSTRIDE; }
            }
        }
        asm volatile("cp.async.commit_group;\n");
        asm volatile("cp.async.wait_group 1;\n");
        __syncthreads();

        if (active) {
            const float* B = &sm[k & 1][0];
            #pragma unroll
            for (int cc = 0; cc < CC; ++cc) {
                const float* s1r = B + cc * CCF;
                const float* s2r = B + cc * CCF + 64 + jyl * WINP;
                unsigned long long a2[4];
                {
                    ulonglong2 t0 = *(const ulonglong2*)&s1r[W0];
                    ulonglong2 t1 = *(const ulonglong2*)&s1r[W0 + 4];
                    a2[0] = t0.x; a2[1] = t0.y; a2[2] = t1.x; a2[3] = t1.y;
                }
                unsigned long long f2[14];
                #pragma unroll
                for (int t = 0; t < 7; ++t) {
                    ulonglong2 v = *(const ulonglong2*)&s2r[wb + 4 * t];
                    f2[2 * t] = v.x; f2[2 * t + 1] = v.y;
                }
                // acc2[j][p] covers out w = W0+2p..2p+1, jx = half*10 + j.
                #pragma unroll
                for (int j = 0; j < 11; ++j)
                    #pragma unroll
                    for (int p = 0; p < 4; ++p)
                        fma2(acc2[j][p], a2[p], f2[j + p]);
            }
        }
        __syncthreads();
    }

    if (active) {
        const float inv = 1.0f / 256.0f;
        const int jy = jylo + jyl;
        #pragma unroll
        for (int j = 0; j < 11; ++j) {
            if (j >= half) {                  // half=1: j=0 duplicates jx=10
                const int jx = half * 10 + j;
                float* o = out + ((((size_t)b * NDISP + (size_t)jy * ND + jx) * NH + h) * NW) + W0;
                float2 u[4];
                #pragma unroll
                for (int p = 0; p < 4; ++p)
                    memcpy(&u[p], &acc2[j][p], 8);
                float4 v0, v1;
                v0.x = u[0].x * inv; v0.y = u[0].y * inv;
                v0.z = u[1].x * inv; v0.w = u[1].y * inv;
                v1.x = u[2].x * inv; v1.y = u[2].y * inv;
                v1.z = u[3].x * inv; v1.w = u[3].y * inv;
                *(float4*)o = v0;
                *(float4*)(o + 4) = v1;
            }
        }
    }
}

extern "C" void kernel_launch(void* const* d_in, const int* in_sizes, int n_in,
                              void* d_out, int out_size) {
    const float* in1 = (const float*)d_in[0];
    const float* in2 = (const float*)d_in[1];
    float* out = (float*)d_out;
    dim3 grid(NH, NB, 2);
    corr_kernel<<<grid, NTHREADS>>>(in1, in2, out);
}